// round 5
// baseline (speedup 1.0000x reference)
#include <cuda_runtime.h>
#include <math.h>

#define BB 16
#define CC 256
#define TT 4096
#define KK 5

// Transposed rp1 weights (exact fp32): g_wt[(c*3 + d)*128 + c2] = rp1_w[c2][c][d]
__device__ float g_wt[CC * 3 * 128];

__global__ void transpose_rp1(const float* __restrict__ rp1_w) {
    int idx = blockIdx.x * blockDim.x + threadIdx.x;
    if (idx >= CC * 3 * 128) return;
    int c2 = idx & 127;
    int cd = idx >> 7;
    int d = cd % 3;
    int c = cd / 3;
    g_wt[idx] = rp1_w[(c2 * CC + c) * 3 + d];
}

// f32x2 helpers ------------------------------------------------------------
__device__ __forceinline__ unsigned long long packf2(float lo, float hi) {
    unsigned long long r;
    asm("mov.b64 %0, {%1, %2};" : "=l"(r) : "f"(lo), "f"(hi));
    return r;
}
__device__ __forceinline__ void unpackf2(unsigned long long v, float& lo, float& hi) {
    asm("mov.b64 {%0, %1}, %2;" : "=f"(lo), "=f"(hi) : "l"(v));
}
#define FFMA2(acc, a, b) asm("fma.rn.f32x2 %0, %1, %2, %0;" : "+l"(acc) : "l"(a), "l"(b))

// ---------------------------------------------------------------------------
// Kernel 1: offset conv (5ch) + modulator conv (5ch) + sigmoid + deformable
// sampling + diagonal einsum -> deformed[b][c][t].  Exact fp32; channel sum
// folded as 32-channel partials to minimize accumulation-order noise (the
// exact-integer knife edge in the sampler amplifies any off-sum noise).
// Block: 128 threads, one t each; grid (T/128, B).
// ---------------------------------------------------------------------------
__global__ __launch_bounds__(128) void k_deform(
    const float* __restrict__ x,
    const float* __restrict__ ow, const float* __restrict__ ob,
    const float* __restrict__ mw, const float* __restrict__ mb,
    const float* __restrict__ weight,
    float* __restrict__ deformed)
{
    __shared__ float s_w[CC * 30];       // [c][k*3+d] offset (j<15) then mod (j>=15)
    __shared__ float s_x[32 * 130];      // 32-channel chunk of x, halo 1 each side

    const int tid = threadIdx.x;
    const int t0 = blockIdx.x * 128;
    const int b = blockIdx.y;
    const float* xb = x + (size_t)b * CC * TT;

    for (int i = tid; i < CC * 30; i += 128) {
        int c = i / 30;
        int j = i - c * 30;
        float v;
        if (j < 15) {
            int k = j / 3, d = j - k * 3;
            v = ow[k * (CC * 3) + c * 3 + d];
        } else {
            int jj = j - 15;
            int k = jj / 3, d = jj - k * 3;
            v = mw[k * (CC * 3) + c * 3 + d];
        }
        s_w[i] = v;
    }

    float offa[KK] = {0.f, 0.f, 0.f, 0.f, 0.f};
    float moda[KK] = {0.f, 0.f, 0.f, 0.f, 0.f};

    for (int cc = 0; cc < CC; cc += 32) {
        __syncthreads();
        for (int idx = tid; idx < 32 * 130; idx += 128) {
            int ci = idx / 130;
            int u = idx - ci * 130;
            int tg = t0 + u - 1;
            s_x[idx] = (tg >= 0 && tg < TT) ? __ldg(xb + (size_t)(cc + ci) * TT + tg) : 0.f;
        }
        __syncthreads();
        // chunk-local partials, folded once per chunk (reduces reorder noise)
        float offc[KK] = {0.f, 0.f, 0.f, 0.f, 0.f};
        float modc[KK] = {0.f, 0.f, 0.f, 0.f, 0.f};
        #pragma unroll 1
        for (int ci = 0; ci < 32; ci++) {
            const float* wrow = s_w + (cc + ci) * 30;
            float x0 = s_x[ci * 130 + tid];
            float x1 = s_x[ci * 130 + tid + 1];
            float x2 = s_x[ci * 130 + tid + 2];
            #pragma unroll
            for (int k = 0; k < KK; k++) {
                offc[k] += x0 * wrow[k * 3 + 0] + x1 * wrow[k * 3 + 1] + x2 * wrow[k * 3 + 2];
                modc[k] += x0 * wrow[15 + k * 3 + 0] + x1 * wrow[15 + k * 3 + 1] + x2 * wrow[15 + k * 3 + 2];
            }
        }
        #pragma unroll
        for (int k = 0; k < KK; k++) { offa[k] += offc[k]; moda[k] += modc[k]; }
    }

    const int t = t0 + tid;
    float mf[KK], mc[KK];
    int pfi[KK], pci[KK];
    #pragma unroll
    for (int k = 0; k < KK; k++) {
        float off = offa[k] + __ldg(ob + k);
        float z = moda[k] + __ldg(mb + k);
        float mod = 1.f / (1.f + expf(-z));
        float pos = (float)(t + k - 2) + off;
        pos = fminf(fmaxf(pos, 0.f), (float)(TT - 1));
        float pf = floorf(pos);
        float pc = ceilf(pos);
        mf[k] = (pc - pos) * mod;   // pos exactly integer -> both weights 0 (matches ref)
        mc[k] = (pos - pf) * mod;
        pfi[k] = (int)pf;
        pci[k] = (int)pc;
    }

    float* db = deformed + (size_t)b * CC * TT;
    #pragma unroll 1
    for (int c = 0; c < CC; c++) {
        const float* xc = xb + (size_t)c * TT;
        const float* dw = weight + ((size_t)c * CC + c) * KK;  // warp-uniform
        float acc = 0.f;
        #pragma unroll
        for (int k = 0; k < KK; k++) {
            float s = __ldg(xc + pfi[k]) * mf[k] + __ldg(xc + pci[k]) * mc[k];
            acc = fmaf(s, __ldg(dw + k), acc);
        }
        db[(size_t)c * TT + t] = acc;
    }
}

// ---------------------------------------------------------------------------
// Kernel 2: h = relu(conv1d(deformed, rp1_w, rp1_b, pad=1)) fused with
// recovery = conv1d(h, rp2_w, rp2_b, pad=0). Packed f32x2 FMAs: each thread
// owns one c2 and 16 t-pairs. Block: 128 threads; grid (T/32, B).
// ---------------------------------------------------------------------------
__global__ __launch_bounds__(128) void k_recover(
    const float* __restrict__ deformed,
    const float* __restrict__ rp1_b,
    const float* __restrict__ rp2_w,
    const float* __restrict__ rp2_b,
    float* __restrict__ recovery)
{
    __shared__ float s_d[CC * 36];   // deformed tile: 34 used (32 t + halo), pad to 36
    __shared__ float s_r[4 * 32];    // per-warp partial recovery sums

    const int tid = threadIdx.x;     // = c2
    const int wid = tid >> 5;
    const int t0 = blockIdx.x * 32;
    const int b = blockIdx.y;
    const float* db = deformed + (size_t)b * CC * TT;

    s_r[tid] = 0.f;

    for (int idx = tid; idx < CC * 36; idx += 128) {
        int c = idx / 36;
        int u = idx - c * 36;
        int tg = t0 + u - 1;
        s_d[idx] = (u < 34 && tg >= 0 && tg < TT) ? db[(size_t)c * TT + tg] : 0.f;
    }
    __syncthreads();

    unsigned long long acc2[16];
    #pragma unroll
    for (int j = 0; j < 16; j++) acc2[j] = 0ull;

    const int c2 = tid;
    #pragma unroll 1
    for (int c = 0; c < CC; c++) {
        const float* wr = g_wt + c * 384 + c2;
        float w0 = __ldg(wr);
        float w1 = __ldg(wr + 128);
        float w2 = __ldg(wr + 256);
        unsigned long long w0p = packf2(w0, w0);
        unsigned long long w1p = packf2(w1, w1);
        unsigned long long w2p = packf2(w2, w2);
        const float2* xs2 = reinterpret_cast<const float2*>(s_d + c * 36);
        float2 e0 = xs2[0];
        unsigned long long ecur = packf2(e0.x, e0.y);
        #pragma unroll
        for (int j = 0; j < 16; j++) {
            float2 e1 = xs2[j + 1];
            unsigned long long enext = packf2(e1.x, e1.y);
            unsigned long long omid  = packf2(e0.y, e1.x);
            FFMA2(acc2[j], ecur, w0p);
            FFMA2(acc2[j], omid, w1p);
            FFMA2(acc2[j], enext, w2p);
            ecur = enext;
            e0 = e1;
        }
    }

    const float b1 = __ldg(rp1_b + c2);
    const float w2c = __ldg(rp2_w + c2);
    float* sr = s_r + wid * 32;
    #pragma unroll
    for (int j = 0; j < 16; j++) {
        float h0, h1;
        unpackf2(acc2[j], h0, h1);
        h0 = fmaxf(h0 + b1, 0.f);
        h1 = fmaxf(h1 + b1, 0.f);
        atomicAdd(sr + 2 * j, h0 * w2c);
        atomicAdd(sr + 2 * j + 1, h1 * w2c);
    }
    __syncthreads();

    if (tid < 32) {
        float r = s_r[tid] + s_r[32 + tid] + s_r[64 + tid] + s_r[96 + tid] + __ldg(rp2_b);
        recovery[(size_t)b * TT + t0 + tid] = r;
    }
}

// ---------------------------------------------------------------------------
extern "C" void kernel_launch(void* const* d_in, const int* in_sizes, int n_in,
                              void* d_out, int out_size) {
    const float* x     = (const float*)d_in[0];
    const float* ow    = (const float*)d_in[1];
    const float* ob    = (const float*)d_in[2];
    const float* mw    = (const float*)d_in[3];
    const float* mb    = (const float*)d_in[4];
    const float* wgt   = (const float*)d_in[5];
    const float* rp1_w = (const float*)d_in[6];
    const float* rp1_b = (const float*)d_in[7];
    const float* rp2_w = (const float*)d_in[8];
    const float* rp2_b = (const float*)d_in[9];

    float* out = (float*)d_out;
    float* deformed = out;                              // (B, C, T)
    float* recovery = out + (size_t)BB * CC * TT;       // (B, T)

    transpose_rp1<<<(CC * 3 * 128 + 255) / 256, 256>>>(rp1_w);
    k_deform<<<dim3(TT / 128, BB), 128>>>(x, ow, ob, mw, mb, wgt, deformed);
    k_recover<<<dim3(TT / 32, BB), 128>>>(deformed, rp1_b, rp2_w, rp2_b, recovery);
}

// round 6
// speedup vs baseline: 1.0971x; 1.0971x over previous
#include <cuda_runtime.h>
#include <math.h>

#define BB 16
#define CC 256
#define TT 4096
#define KK 5

// Packed duplicated rp1 weights: g_wt2[(c*3 + d)*128 + c2] = (w,w) as f32x2,
// where w = rp1_w[c2][c][d].
__device__ unsigned long long g_wt2[CC * 3 * 128];

__global__ void transpose_rp1(const float* __restrict__ rp1_w) {
    int idx = blockIdx.x * blockDim.x + threadIdx.x;
    if (idx >= CC * 3 * 128) return;
    int c2 = idx & 127;
    int cd = idx >> 7;
    int d = cd % 3;
    int c = cd / 3;
    float w = rp1_w[(c2 * CC + c) * 3 + d];
    unsigned long long p;
    asm("mov.b64 %0, {%1, %2};" : "=l"(p) : "f"(w), "f"(w));
    g_wt2[idx] = p;
}

#define FFMA2(acc, a, b) asm("fma.rn.f32x2 %0, %1, %2, %0;" : "+l"(acc) : "l"(a), "l"(b))

__device__ __forceinline__ void unpackf2(unsigned long long v, float& lo, float& hi) {
    asm("mov.b64 {%0, %1}, %2;" : "=f"(lo), "=f"(hi) : "l"(v));
}

// ---------------------------------------------------------------------------
// Kernel 1: offset conv (5ch) + modulator conv (5ch) + sigmoid + deformable
// sampling + diagonal einsum -> deformed[b][c][t].  UNCHANGED from round 5
// (chunk-folded fp32 accumulation — numerics frozen; knife-edge sensitive).
// ---------------------------------------------------------------------------
__global__ __launch_bounds__(128) void k_deform(
    const float* __restrict__ x,
    const float* __restrict__ ow, const float* __restrict__ ob,
    const float* __restrict__ mw, const float* __restrict__ mb,
    const float* __restrict__ weight,
    float* __restrict__ deformed)
{
    __shared__ float s_w[CC * 30];
    __shared__ float s_x[32 * 130];

    const int tid = threadIdx.x;
    const int t0 = blockIdx.x * 128;
    const int b = blockIdx.y;
    const float* xb = x + (size_t)b * CC * TT;

    for (int i = tid; i < CC * 30; i += 128) {
        int c = i / 30;
        int j = i - c * 30;
        float v;
        if (j < 15) {
            int k = j / 3, d = j - k * 3;
            v = ow[k * (CC * 3) + c * 3 + d];
        } else {
            int jj = j - 15;
            int k = jj / 3, d = jj - k * 3;
            v = mw[k * (CC * 3) + c * 3 + d];
        }
        s_w[i] = v;
    }

    float offa[KK] = {0.f, 0.f, 0.f, 0.f, 0.f};
    float moda[KK] = {0.f, 0.f, 0.f, 0.f, 0.f};

    for (int cc = 0; cc < CC; cc += 32) {
        __syncthreads();
        for (int idx = tid; idx < 32 * 130; idx += 128) {
            int ci = idx / 130;
            int u = idx - ci * 130;
            int tg = t0 + u - 1;
            s_x[idx] = (tg >= 0 && tg < TT) ? __ldg(xb + (size_t)(cc + ci) * TT + tg) : 0.f;
        }
        __syncthreads();
        float offc[KK] = {0.f, 0.f, 0.f, 0.f, 0.f};
        float modc[KK] = {0.f, 0.f, 0.f, 0.f, 0.f};
        #pragma unroll 1
        for (int ci = 0; ci < 32; ci++) {
            const float* wrow = s_w + (cc + ci) * 30;
            float x0 = s_x[ci * 130 + tid];
            float x1 = s_x[ci * 130 + tid + 1];
            float x2 = s_x[ci * 130 + tid + 2];
            #pragma unroll
            for (int k = 0; k < KK; k++) {
                offc[k] += x0 * wrow[k * 3 + 0] + x1 * wrow[k * 3 + 1] + x2 * wrow[k * 3 + 2];
                modc[k] += x0 * wrow[15 + k * 3 + 0] + x1 * wrow[15 + k * 3 + 1] + x2 * wrow[15 + k * 3 + 2];
            }
        }
        #pragma unroll
        for (int k = 0; k < KK; k++) { offa[k] += offc[k]; moda[k] += modc[k]; }
    }

    const int t = t0 + tid;
    float mf[KK], mc[KK];
    int pfi[KK], pci[KK];
    #pragma unroll
    for (int k = 0; k < KK; k++) {
        float off = offa[k] + __ldg(ob + k);
        float z = moda[k] + __ldg(mb + k);
        float mod = 1.f / (1.f + expf(-z));
        float pos = (float)(t + k - 2) + off;
        pos = fminf(fmaxf(pos, 0.f), (float)(TT - 1));
        float pf = floorf(pos);
        float pc = ceilf(pos);
        mf[k] = (pc - pos) * mod;
        mc[k] = (pos - pf) * mod;
        pfi[k] = (int)pf;
        pci[k] = (int)pc;
    }

    float* db = deformed + (size_t)b * CC * TT;
    #pragma unroll 1
    for (int c = 0; c < CC; c++) {
        const float* xc = xb + (size_t)c * TT;
        const float* dw = weight + ((size_t)c * CC + c) * KK;
        float acc = 0.f;
        #pragma unroll
        for (int k = 0; k < KK; k++) {
            float s = __ldg(xc + pfi[k]) * mf[k] + __ldg(xc + pci[k]) * mc[k];
            acc = fmaf(s, __ldg(dw + k), acc);
        }
        db[(size_t)c * TT + t] = acc;
    }
}

// ---------------------------------------------------------------------------
// Kernel 2: h = relu(conv1d(deformed, rp1_w, rp1_b, pad=1)) fused with
// recovery = conv1d(h, rp2_w, rp2_b, pad=0).
// Rewritten: dual smem copies (aligned + shifted) -> all taps are aligned
// f32x2 pairs, loaded 16B at a time; packed weights prefetched; atomic-free
// transpose reduction. Block: 128 threads = one c2 each, 32-t tile.
// Dynamic smem: copyA 256*32 floats + copyB 256*36 floats = 69632 B.
// ---------------------------------------------------------------------------
#define SMEM_FLOATS (CC * 32 + CC * 36)

__global__ __launch_bounds__(128) void k_recover(
    const float* __restrict__ deformed,
    const float* __restrict__ rp1_b,
    const float* __restrict__ rp2_w,
    const float* __restrict__ rp2_b,
    float* __restrict__ recovery)
{
    extern __shared__ float dsm[];
    float* sA = dsm;              // [c][v], v=0..31 : x[t0+v], stride 32
    float* sB = dsm + CC * 32;    // [c][u], u=0..33 : x[t0-1+u], stride 36 (pad)
    __shared__ float sp[4 * 33];  // per-warp partial recovery sums

    const int tid = threadIdx.x;  // = c2
    const int t0 = blockIdx.x * 32;
    const int b = blockIdx.y;
    const float* db = deformed + (size_t)b * CC * TT;

    // Stage both copies
    for (int idx = tid; idx < CC * 34; idx += 128) {
        int c = idx / 34;
        int u = idx - c * 34;
        int tg = t0 + u - 1;
        float v = (tg >= 0 && tg < TT) ? db[(size_t)c * TT + tg] : 0.f;
        sB[c * 36 + u] = v;
        int vv = u - 1;
        if (vv >= 0 && vv < 32) sA[c * 32 + vv] = v;
    }
    __syncthreads();

    unsigned long long acc2[16];
    #pragma unroll
    for (int j = 0; j < 16; j++) acc2[j] = 0ull;

    const int c2 = tid;
    const unsigned long long* W = g_wt2 + c2;
    unsigned long long w0n = __ldg(W);
    unsigned long long w1n = __ldg(W + 128);
    unsigned long long w2n = __ldg(W + 256);

    #pragma unroll 1
    for (int c = 0; c < CC; c++) {
        unsigned long long w0p = w0n, w1p = w1n, w2p = w2n;
        if (c < CC - 1) {
            const unsigned long long* Wn = W + (c + 1) * 384;
            w0n = __ldg(Wn);
            w1n = __ldg(Wn + 128);
            w2n = __ldg(Wn + 256);
        }
        const ulonglong2* A128 = reinterpret_cast<const ulonglong2*>(sA + c * 32);
        const ulonglong2* B128 = reinterpret_cast<const ulonglong2*>(sB + c * 36);
        ulonglong2 bq = B128[0];
        #pragma unroll
        for (int q = 0; q < 8; q++) {
            ulonglong2 aq = A128[q];
            ulonglong2 bq1 = B128[q + 1];
            // j = 2q : left=(x2j-1,x2j)=bq.x  center=aq.x  right=(x2j+1,x2j+2)=bq.y
            FFMA2(acc2[2 * q], bq.x, w0p);
            FFMA2(acc2[2 * q], aq.x, w1p);
            FFMA2(acc2[2 * q], bq.y, w2p);
            // j = 2q+1 : left=bq.y  center=aq.y  right=bq1.x
            FFMA2(acc2[2 * q + 1], bq.y, w0p);
            FFMA2(acc2[2 * q + 1], aq.y, w1p);
            FFMA2(acc2[2 * q + 1], bq1.x, w2p);
            bq = bq1;
        }
    }

    const float b1 = __ldg(rp1_b + c2);
    const float w2c = __ldg(rp2_w + c2);

    // Atomic-free reduction: scratch[t][c2] (stride 129, conflict-free)
    __syncthreads();
    float* sc = dsm;   // reuse: needs 32*129 = 4128 floats << SMEM_FLOATS
    #pragma unroll
    for (int j = 0; j < 16; j++) {
        float h0, h1;
        unpackf2(acc2[j], h0, h1);
        h0 = fmaxf(h0 + b1, 0.f) * w2c;
        h1 = fmaxf(h1 + b1, 0.f) * w2c;
        sc[(2 * j) * 129 + c2] = h0;
        sc[(2 * j + 1) * 129 + c2] = h1;
    }
    __syncthreads();

    {
        int tl = tid & 31;        // t_local
        int w = tid >> 5;         // c2 group
        const float* row = sc + tl * 129 + w * 32;
        float s = 0.f;
        #pragma unroll
        for (int i = 0; i < 32; i++) s += row[i];
        sp[w * 33 + tl] = s;
    }
    __syncthreads();

    if (tid < 32) {
        float r = sp[tid] + sp[33 + tid] + sp[66 + tid] + sp[99 + tid] + __ldg(rp2_b);
        recovery[(size_t)b * TT + t0 + tid] = r;
    }
}

// ---------------------------------------------------------------------------
extern "C" void kernel_launch(void* const* d_in, const int* in_sizes, int n_in,
                              void* d_out, int out_size) {
    const float* x     = (const float*)d_in[0];
    const float* ow    = (const float*)d_in[1];
    const float* ob    = (const float*)d_in[2];
    const float* mw    = (const float*)d_in[3];
    const float* mb    = (const float*)d_in[4];
    const float* wgt   = (const float*)d_in[5];
    const float* rp1_w = (const float*)d_in[6];
    const float* rp1_b = (const float*)d_in[7];
    const float* rp2_w = (const float*)d_in[8];
    const float* rp2_b = (const float*)d_in[9];

    float* out = (float*)d_out;
    float* deformed = out;                              // (B, C, T)
    float* recovery = out + (size_t)BB * CC * TT;       // (B, T)

    static bool attr_set = false;
    if (!attr_set) {
        cudaFuncSetAttribute(k_recover, cudaFuncAttributeMaxDynamicSharedMemorySize,
                             SMEM_FLOATS * (int)sizeof(float));
        attr_set = true;
    }

    transpose_rp1<<<(CC * 3 * 128 + 255) / 256, 256>>>(rp1_w);
    k_deform<<<dim3(TT / 128, BB), 128>>>(x, ow, ob, mw, mb, wgt, deformed);
    k_recover<<<dim3(TT / 32, BB), 128, SMEM_FLOATS * sizeof(float)>>>(
        deformed, rp1_b, rp2_w, rp2_b, recovery);
}

// round 7
// speedup vs baseline: 1.2113x; 1.1041x over previous
#include <cuda_runtime.h>
#include <math.h>

#define BB 16
#define CC 256
#define TT 4096
#define KK 5

#define WIN  166   // staged window per channel: x[t0-16 .. t0+149]
#define WOFF 16

// Packed duplicated rp1 weights: g_wt2[(c*3 + d)*128 + c2] = (w,w) as f32x2.
__device__ unsigned long long g_wt2[CC * 3 * 128];

__global__ void transpose_rp1(const float* __restrict__ rp1_w) {
    int idx = blockIdx.x * blockDim.x + threadIdx.x;
    if (idx >= CC * 3 * 128) return;
    int c2 = idx & 127;
    int cd = idx >> 7;
    int d = cd % 3;
    int c = cd / 3;
    float w = rp1_w[(c2 * CC + c) * 3 + d];
    unsigned long long p;
    asm("mov.b64 %0, {%1, %2};" : "=l"(p) : "f"(w), "f"(w));
    g_wt2[idx] = p;
}

#define FFMA2(acc, a, b) asm("fma.rn.f32x2 %0, %1, %2, %0;" : "+l"(acc) : "l"(a), "l"(b))

__device__ __forceinline__ void unpackf2(unsigned long long v, float& lo, float& hi) {
    asm("mov.b64 {%0, %1}, %2;" : "=f"(lo), "=f"(hi) : "l"(v));
}

// ---------------------------------------------------------------------------
// Kernel 1: offset/modulator convs + sigmoid + deformable sampling + diag
// einsum -> deformed[b][c][t].  Numerics (values + fma order) identical to
// round 5/6 — knife-edge frozen.  Phase B now gathers from a staged smem
// window (warp-voted fast path; __ldg fallback preserves correctness).
// Dynamic smem: s_w 256*30 | s_dw 256*5 | s_b 32*WIN  = 14272 floats (57KB).
// ---------------------------------------------------------------------------
#define DEF_SMEM_FLOATS (CC * 30 + CC * KK + 32 * WIN)

__global__ __launch_bounds__(128) void k_deform(
    const float* __restrict__ x,
    const float* __restrict__ ow, const float* __restrict__ ob,
    const float* __restrict__ mw, const float* __restrict__ mb,
    const float* __restrict__ weight,
    float* __restrict__ deformed)
{
    extern __shared__ float dsm_d[];
    float* s_w  = dsm_d;                    // [c][k*3+d], offset (j<15) then mod
    float* s_dw = dsm_d + CC * 30;          // diag weights [c][k]
    float* s_b  = dsm_d + CC * 30 + CC * KK; // window [ci][WIN]

    const int tid = threadIdx.x;
    const int t0 = blockIdx.x * 128;
    const int b = blockIdx.y;
    const float* xb = x + (size_t)b * CC * TT;

    for (int i = tid; i < CC * 30; i += 128) {
        int c = i / 30;
        int j = i - c * 30;
        float v;
        if (j < 15) {
            int k = j / 3, d = j - k * 3;
            v = ow[k * (CC * 3) + c * 3 + d];
        } else {
            int jj = j - 15;
            int k = jj / 3, d = jj - k * 3;
            v = mw[k * (CC * 3) + c * 3 + d];
        }
        s_w[i] = v;
    }

    float offa[KK] = {0.f, 0.f, 0.f, 0.f, 0.f};
    float moda[KK] = {0.f, 0.f, 0.f, 0.f, 0.f};

    // Phase A: 10-channel conv (chunk-folded fp32 accumulation — frozen)
    for (int cc = 0; cc < CC; cc += 32) {
        __syncthreads();
        for (int idx = tid; idx < 32 * WIN; idx += 128) {
            int ci = idx / WIN;
            int u = idx - ci * WIN;
            int tg = t0 - WOFF + u;
            s_b[idx] = (tg >= 0 && tg < TT) ? __ldg(xb + (size_t)(cc + ci) * TT + tg) : 0.f;
        }
        __syncthreads();
        float offc[KK] = {0.f, 0.f, 0.f, 0.f, 0.f};
        float modc[KK] = {0.f, 0.f, 0.f, 0.f, 0.f};
        #pragma unroll 1
        for (int ci = 0; ci < 32; ci++) {
            const float* wrow = s_w + (cc + ci) * 30;
            const float* xs = s_b + ci * WIN + tid + (WOFF - 1);
            float x0 = xs[0];
            float x1 = xs[1];
            float x2 = xs[2];
            #pragma unroll
            for (int k = 0; k < KK; k++) {
                offc[k] += x0 * wrow[k * 3 + 0] + x1 * wrow[k * 3 + 1] + x2 * wrow[k * 3 + 2];
                modc[k] += x0 * wrow[15 + k * 3 + 0] + x1 * wrow[15 + k * 3 + 1] + x2 * wrow[15 + k * 3 + 2];
            }
        }
        #pragma unroll
        for (int k = 0; k < KK; k++) { offa[k] += offc[k]; moda[k] += modc[k]; }
    }

    // positions / interp weights (exact fp32 — frozen)
    const int t = t0 + tid;
    float mf[KK], mc[KK];
    int pfi[KK], pci[KK];
    #pragma unroll
    for (int k = 0; k < KK; k++) {
        float off = offa[k] + __ldg(ob + k);
        float z = moda[k] + __ldg(mb + k);
        float mod = 1.f / (1.f + expf(-z));
        float pos = (float)(t + k - 2) + off;
        pos = fminf(fmaxf(pos, 0.f), (float)(TT - 1));
        float pf = floorf(pos);
        float pc = ceilf(pos);
        mf[k] = (pc - pos) * mod;
        mc[k] = (pos - pf) * mod;
        pfi[k] = (int)pf;
        pci[k] = (int)pc;
    }

    // window indices + warp vote (off is ~N(0,1.4): out-of-window ~1e-22/sample)
    int idxf[KK], idxc[KK];
    bool allin = true;
    #pragma unroll
    for (int k = 0; k < KK; k++) {
        idxf[k] = pfi[k] - (t0 - WOFF);
        idxc[k] = pci[k] - (t0 - WOFF);
        allin = allin && ((unsigned)idxf[k] < (unsigned)WIN) && ((unsigned)idxc[k] < (unsigned)WIN);
    }
    const bool fast = __all_sync(0xffffffffu, allin);

    // stage diag weights
    __syncthreads();
    for (int i = tid; i < CC * KK; i += 128) {
        int c = i / KK;
        int k = i - c * KK;
        s_dw[i] = __ldg(weight + ((size_t)c * CC + c) * KK + k);
    }

    // Phase B: sample + diag einsum, chunk-staged windows
    float* db = deformed + (size_t)b * CC * TT;
    for (int cc = 0; cc < CC; cc += 32) {
        __syncthreads();
        for (int idx = tid; idx < 32 * WIN; idx += 128) {
            int ci = idx / WIN;
            int u = idx - ci * WIN;
            int tg = t0 - WOFF + u;
            s_b[idx] = (tg >= 0 && tg < TT) ? __ldg(xb + (size_t)(cc + ci) * TT + tg) : 0.f;
        }
        __syncthreads();
        if (fast) {
            #pragma unroll 2
            for (int ci = 0; ci < 32; ci++) {
                const float* xs = s_b + ci * WIN;
                const float* dwc = s_dw + (cc + ci) * KK;
                float acc = 0.f;
                #pragma unroll
                for (int k = 0; k < KK; k++) {
                    float s = xs[idxf[k]] * mf[k] + xs[idxc[k]] * mc[k];
                    acc = fmaf(s, dwc[k], acc);
                }
                db[(size_t)(cc + ci) * TT + t] = acc;
            }
        } else {
            #pragma unroll 1
            for (int ci = 0; ci < 32; ci++) {
                const float* xc = xb + (size_t)(cc + ci) * TT;
                const float* dwc = s_dw + (cc + ci) * KK;
                float acc = 0.f;
                #pragma unroll
                for (int k = 0; k < KK; k++) {
                    float s = __ldg(xc + pfi[k]) * mf[k] + __ldg(xc + pci[k]) * mc[k];
                    acc = fmaf(s, dwc[k], acc);
                }
                db[(size_t)(cc + ci) * TT + t] = acc;
            }
        }
    }
}

// ---------------------------------------------------------------------------
// Kernel 2: UNCHANGED from round 6 (dual smem copies + f32x2 + transpose
// reduction). Dynamic smem 69632 B.
// ---------------------------------------------------------------------------
#define REC_SMEM_FLOATS (CC * 32 + CC * 36)

__global__ __launch_bounds__(128) void k_recover(
    const float* __restrict__ deformed,
    const float* __restrict__ rp1_b,
    const float* __restrict__ rp2_w,
    const float* __restrict__ rp2_b,
    float* __restrict__ recovery)
{
    extern __shared__ float dsm[];
    float* sA = dsm;              // [c][v], v=0..31 : x[t0+v], stride 32
    float* sB = dsm + CC * 32;    // [c][u], u=0..33 : x[t0-1+u], stride 36 (pad)
    __shared__ float sp[4 * 33];

    const int tid = threadIdx.x;  // = c2
    const int t0 = blockIdx.x * 32;
    const int b = blockIdx.y;
    const float* db = deformed + (size_t)b * CC * TT;

    for (int idx = tid; idx < CC * 34; idx += 128) {
        int c = idx / 34;
        int u = idx - c * 34;
        int tg = t0 + u - 1;
        float v = (tg >= 0 && tg < TT) ? db[(size_t)c * TT + tg] : 0.f;
        sB[c * 36 + u] = v;
        int vv = u - 1;
        if (vv >= 0 && vv < 32) sA[c * 32 + vv] = v;
    }
    __syncthreads();

    unsigned long long acc2[16];
    #pragma unroll
    for (int j = 0; j < 16; j++) acc2[j] = 0ull;

    const int c2 = tid;
    const unsigned long long* W = g_wt2 + c2;
    unsigned long long w0n = __ldg(W);
    unsigned long long w1n = __ldg(W + 128);
    unsigned long long w2n = __ldg(W + 256);

    #pragma unroll 1
    for (int c = 0; c < CC; c++) {
        unsigned long long w0p = w0n, w1p = w1n, w2p = w2n;
        if (c < CC - 1) {
            const unsigned long long* Wn = W + (c + 1) * 384;
            w0n = __ldg(Wn);
            w1n = __ldg(Wn + 128);
            w2n = __ldg(Wn + 256);
        }
        const ulonglong2* A128 = reinterpret_cast<const ulonglong2*>(sA + c * 32);
        const ulonglong2* B128 = reinterpret_cast<const ulonglong2*>(sB + c * 36);
        ulonglong2 bq = B128[0];
        #pragma unroll
        for (int q = 0; q < 8; q++) {
            ulonglong2 aq = A128[q];
            ulonglong2 bq1 = B128[q + 1];
            FFMA2(acc2[2 * q], bq.x, w0p);
            FFMA2(acc2[2 * q], aq.x, w1p);
            FFMA2(acc2[2 * q], bq.y, w2p);
            FFMA2(acc2[2 * q + 1], bq.y, w0p);
            FFMA2(acc2[2 * q + 1], aq.y, w1p);
            FFMA2(acc2[2 * q + 1], bq1.x, w2p);
            bq = bq1;
        }
    }

    const float b1 = __ldg(rp1_b + c2);
    const float w2c = __ldg(rp2_w + c2);

    __syncthreads();
    float* sc = dsm;   // reuse: 32*129 floats
    #pragma unroll
    for (int j = 0; j < 16; j++) {
        float h0, h1;
        unpackf2(acc2[j], h0, h1);
        h0 = fmaxf(h0 + b1, 0.f) * w2c;
        h1 = fmaxf(h1 + b1, 0.f) * w2c;
        sc[(2 * j) * 129 + c2] = h0;
        sc[(2 * j + 1) * 129 + c2] = h1;
    }
    __syncthreads();

    {
        int tl = tid & 31;
        int w = tid >> 5;
        const float* row = sc + tl * 129 + w * 32;
        float s = 0.f;
        #pragma unroll
        for (int i = 0; i < 32; i++) s += row[i];
        sp[w * 33 + tl] = s;
    }
    __syncthreads();

    if (tid < 32) {
        float r = sp[tid] + sp[33 + tid] + sp[66 + tid] + sp[99 + tid] + __ldg(rp2_b);
        recovery[(size_t)b * TT + t0 + tid] = r;
    }
}

// ---------------------------------------------------------------------------
extern "C" void kernel_launch(void* const* d_in, const int* in_sizes, int n_in,
                              void* d_out, int out_size) {
    const float* x     = (const float*)d_in[0];
    const float* ow    = (const float*)d_in[1];
    const float* ob    = (const float*)d_in[2];
    const float* mw    = (const float*)d_in[3];
    const float* mb    = (const float*)d_in[4];
    const float* wgt   = (const float*)d_in[5];
    const float* rp1_w = (const float*)d_in[6];
    const float* rp1_b = (const float*)d_in[7];
    const float* rp2_w = (const float*)d_in[8];
    const float* rp2_b = (const float*)d_in[9];

    float* out = (float*)d_out;
    float* deformed = out;                              // (B, C, T)
    float* recovery = out + (size_t)BB * CC * TT;       // (B, T)

    cudaFuncSetAttribute(k_deform, cudaFuncAttributeMaxDynamicSharedMemorySize,
                         DEF_SMEM_FLOATS * (int)sizeof(float));
    cudaFuncSetAttribute(k_recover, cudaFuncAttributeMaxDynamicSharedMemorySize,
                         REC_SMEM_FLOATS * (int)sizeof(float));

    // Order: D, T, R — T still precedes R in-stream; shifts ncu's capture slot
    // off transpose_rp1 so the next profile shows a hot kernel.
    k_deform<<<dim3(TT / 128, BB), 128, DEF_SMEM_FLOATS * sizeof(float)>>>(
        x, ow, ob, mw, mb, wgt, deformed);
    transpose_rp1<<<(CC * 3 * 128 + 255) / 256, 256>>>(rp1_w);
    k_recover<<<dim3(TT / 32, BB), 128, REC_SMEM_FLOATS * sizeof(float)>>>(
        deformed, rp1_b, rp2_w, rp2_b, recovery);
}